// round 10
// baseline (speedup 1.0000x reference)
#include <cuda_runtime.h>
#include <cuda_fp16.h>
#include <cstdint>

#define B_MAX 65536

// ---------------- device scratch (no allocs allowed) ----------------
// repacked weights (fp16): [l][half][row:128][k:136] ; global row r = half*128+row = n'=4j+gate
__device__ __align__(16) __half g_wm[4][2][128][136];
__device__ float g_init[(size_t)B_MAX * 128];   // [b][128] = (h0 | c0)

// ---------------- math ----------------
__device__ __forceinline__ float sigm(float x) { return __fdividef(1.f, 1.f + __expf(-x)); }
__device__ __forceinline__ float tanh_(float x) {
    float ax = fabsf(x);
    float e = __expf(-2.f * ax);
    return copysignf(__fdividef(1.f - e, 1.f + e), x);
}

// ---------------- PTX helpers (portable sm_80+) ----------------
__device__ __forceinline__ uint32_t s32(const void* p) { return (uint32_t)__cvta_generic_to_shared(p); }
__device__ __forceinline__ void cp16(uint32_t dst, const void* src) {
    asm volatile("cp.async.cg.shared.global [%0], [%1], 16;" :: "r"(dst), "l"(src));
}
__device__ __forceinline__ void cp_commit() { asm volatile("cp.async.commit_group;" ::: "memory"); }
__device__ __forceinline__ void cp_wait1()  { asm volatile("cp.async.wait_group 1;" ::: "memory"); }

__device__ __forceinline__ void ldsm4(uint32_t r[4], uint32_t addr) {
    asm volatile("ldmatrix.sync.aligned.m8n8.x4.shared.b16 {%0,%1,%2,%3}, [%4];"
        : "=r"(r[0]), "=r"(r[1]), "=r"(r[2]), "=r"(r[3]) : "r"(addr));
}
__device__ __forceinline__ void mma16816(float d[4], const uint32_t a[4], uint32_t b0, uint32_t b1) {
    asm volatile("mma.sync.aligned.m16n8k16.row.col.f32.f16.f16.f32 "
        "{%0,%1,%2,%3}, {%4,%5,%6,%7}, {%8,%9}, {%0,%1,%2,%3};"
        : "+f"(d[0]), "+f"(d[1]), "+f"(d[2]), "+f"(d[3])
        : "r"(a[0]), "r"(a[1]), "r"(a[2]), "r"(a[3]), "r"(b0), "r"(b1));
}

#define BAR_ARRIVE(id, cnt) asm volatile("bar.arrive %0, %1;" :: "r"(id), "r"(cnt) : "memory")
#define BAR_SYNC(id, cnt)   asm volatile("bar.sync %0, %1;"   :: "r"(id), "r"(cnt) : "memory")

// ---------------- SMEM layout (bytes from 1024-aligned base) ----------------
#define W_HALF   34816    // 128 rows x 272B
#define OFF_HHI  0        // [l:4][m:64][k:72] fp16 = 36864
#define OFF_HLO  36864    // 36864
#define OFF_W    73728    // 2 x 34816 = 69632
#define OFF_GT   143360   // Gt[n':256][m:66 pad] f32 = 67584
#define OFF_BIAS 210944   // [4][256] f32 = 4096
#define OFF_WI0  215040   // [256][3] f32 = 3072
#define OFF_WO   218112   // [3][64] f32 = 768
#define OFF_BO   218880   // 16
#define OFF_X    218896   // [3][64] f32 = 768
#define SMEM_USE 219664
#define SMEM_REQ (SMEM_USE + 1024)

// ---------------- prologue 1: weight repack ----------------
__global__ void repack_k(const float* __restrict__ W_hh, const float* __restrict__ W_ih_rest) {
    int idx = blockIdx.x * blockDim.x + threadIdx.x;
    if (idx >= 4 * 256 * 136) return;
    int kc = idx % 136, r = (idx / 136) & 255, l = idx / (136 * 256);
    float v = 0.f;
    if (kc < 128) {
        int j = r >> 2, g = r & 3, n = g * 64 + j;
        if (kc < 64)      v = W_hh[(l * 256 + n) * 64 + kc];
        else if (l > 0)   v = W_ih_rest[((l - 1) * 256 + n) * 64 + (kc - 64)];
    }
    g_wm[l][r >> 7][r & 127][kc] = __float2half(v);
}

// ---------------- prologue 2: decoder_fc -> (h0|c0) ----------------
__global__ void embed_k(const float* __restrict__ conds,
                        const float* __restrict__ W1, const float* __restrict__ b1,
                        const float* __restrict__ W2, const float* __restrict__ b2) {
    int b = blockIdx.x;
    __shared__ float hid[64];
    __shared__ float cnd[8];
    int t = threadIdx.x;  // 128
    if (t < 8) cnd[t] = conds[b * 8 + t];
    __syncthreads();
    if (t < 64) {
        float a = b1[t];
        #pragma unroll
        for (int k = 0; k < 8; k++) a += cnd[k] * W1[t * 8 + k];
        hid[t] = fmaxf(a, 0.f);
    }
    __syncthreads();
    float a = b2[t];
    #pragma unroll
    for (int k = 0; k < 64; k++) a += hid[k] * W2[t * 64 + k];
    g_init[(size_t)b * 128 + t] = a;
}

// stage one half-image (34816 B) into its buffer — MMA threads (tid<256)
__device__ __forceinline__ void stageWh(uint32_t wS, int l, int half, int tid) {
    uint32_t dst = wS + (uint32_t)(half * W_HALF);
    const char* src = (const char*)&g_wm[l][half][0][0];
    #pragma unroll
    for (int n = 0; n < 8; n++)
        cp16(dst + (uint32_t)(tid * 16 + n * 4096), src + tid * 16 + n * 4096);
    if (tid < 128) cp16(dst + (uint32_t)(32768 + tid * 16), src + 32768 + tid * 16);
    cp_commit();
}

// One K=64 block for one N-half: both A passes (hi+lo), shared B fragments.
// np covers 2 x 16 rows (warp owns 32 rows of the half).
#define CHUNK2H(AHI, ALO, KS0, WBASE)                                                  \
{                                                                                      \
    _Pragma("unroll")                                                                  \
    for (int ki = 0; ki < 4; ki++) {                                                   \
        uint32_t ah_[2][4], al_[2][4];                                                 \
        _Pragma("unroll")                                                              \
        for (int mt = 0; mt < 2; mt++) {                                               \
            ldsm4(ah_[mt], (AHI) + (uint32_t)((m0w + mt * 16) * 144 + ki * 32) + a_laneoff); \
            ldsm4(al_[mt], (ALO) + (uint32_t)((m0w + mt * 16) * 144 + ki * 32) + a_laneoff); \
        }                                                                              \
        _Pragma("unroll")                                                              \
        for (int np = 0; np < 2; np++) {                                               \
            uint32_t bf_[4];                                                           \
            ldsm4(bf_, (WBASE) + (uint32_t)((n0w + np * 16) * 272 + ((KS0) + ki) * 32) + b_laneoff); \
            _Pragma("unroll")                                                          \
            for (int mt = 0; mt < 2; mt++) {                                           \
                mma16816(acc[mt][2 * np],     ah_[mt], bf_[0], bf_[2]);                \
                mma16816(acc[mt][2 * np + 1], ah_[mt], bf_[1], bf_[3]);                \
                mma16816(acc[mt][2 * np],     al_[mt], bf_[0], bf_[2]);                \
                mma16816(acc[mt][2 * np + 1], al_[mt], bf_[1], bf_[3]);                \
            }                                                                          \
        }                                                                              \
    }                                                                                  \
}

#define GT_STORE(HALF)                                                                 \
{                                                                                      \
    _Pragma("unroll")                                                                  \
    for (int mt = 0; mt < 2; mt++)                                                     \
        _Pragma("unroll")                                                              \
        for (int nt = 0; nt < 4; nt++) {                                               \
            int col = (HALF) * 128 + n0w + nt * 8 + 2 * tig;                           \
            int row = m0w + mt * 16 + gid;                                             \
            GtS[col * 66 + row]           = acc[mt][nt][0];                            \
            GtS[(col + 1) * 66 + row]     = acc[mt][nt][1];                            \
            GtS[col * 66 + row + 8]       = acc[mt][nt][2];                            \
            GtS[(col + 1) * 66 + row + 8] = acc[mt][nt][3];                            \
        }                                                                              \
}

#define ACC_ZERO()                                                                     \
{                                                                                      \
    _Pragma("unroll")                                                                  \
    for (int mt = 0; mt < 2; mt++)                                                     \
        _Pragma("unroll")                                                              \
        for (int nt = 0; nt < 4; nt++)                                                 \
            _Pragma("unroll")                                                          \
            for (int q = 0; q < 4; q++) acc[mt][nt][q] = 0.f;                          \
}

// epilogue for layer L with c-register array CR (EPI threads: b, jg)
#define EPI(L, CR)                                                                     \
{                                                                                      \
    float x0 = 0.f, x1 = 0.f, x2 = 0.f;                                                \
    if ((L) == 0) { x0 = xS[b]; x1 = xS[64 + b]; x2 = xS[128 + b]; }                   \
    _Pragma("unroll")                                                                  \
    for (int jj = 0; jj < 16; jj++) {                                                  \
        int j = jg * 16 + jj;                                                          \
        float vi = GtS[(4 * j + 0) * 66 + b] + biasS[(L) * 256 + j];                   \
        float vf = GtS[(4 * j + 1) * 66 + b] + biasS[(L) * 256 + 64 + j];              \
        float vg = GtS[(4 * j + 2) * 66 + b] + biasS[(L) * 256 + 128 + j];             \
        float vo = GtS[(4 * j + 3) * 66 + b] + biasS[(L) * 256 + 192 + j];             \
        if ((L) == 0) {                                                                \
            vi += x0 * wi0S[j * 3] + x1 * wi0S[j * 3 + 1] + x2 * wi0S[j * 3 + 2];      \
            vf += x0 * wi0S[(64 + j) * 3] + x1 * wi0S[(64 + j) * 3 + 1] + x2 * wi0S[(64 + j) * 3 + 2];   \
            vg += x0 * wi0S[(128 + j) * 3] + x1 * wi0S[(128 + j) * 3 + 1] + x2 * wi0S[(128 + j) * 3 + 2]; \
            vo += x0 * wi0S[(192 + j) * 3] + x1 * wi0S[(192 + j) * 3 + 1] + x2 * wi0S[(192 + j) * 3 + 2]; \
        }                                                                              \
        float cn = sigm(vf) * CR[jj] + sigm(vi) * tanh_(vg);                           \
        CR[jj] = cn;                                                                   \
        float hn = sigm(vo) * tanh_(cn);                                               \
        __half bh = __float2half(hn);                                                  \
        __half bl = __float2half(hn - __half2float(bh));                               \
        hHiE[((L) * 64 + b) * 72 + j] = bh;                                            \
        hLoE[((L) * 64 + b) * 72 + j] = bl;                                            \
    }                                                                                  \
}

__global__ __launch_bounds__(512, 1)
void lstm_main(const float* __restrict__ b_ih, const float* __restrict__ b_hh,
               const float* __restrict__ W_ih0,
               const float* __restrict__ Wo, const float* __restrict__ bo,
               float* __restrict__ out, int T) {
    extern __shared__ char raw[];
    char* basep = (char*)(((uintptr_t)raw + 1023) & ~(uintptr_t)1023);
    const uint32_t hHiS = s32(basep + OFF_HHI);
    const uint32_t hLoS = s32(basep + OFF_HLO);
    const uint32_t wS   = s32(basep + OFF_W);
    __half* hHiE = (__half*)(basep + OFF_HHI);
    __half* hLoE = (__half*)(basep + OFF_HLO);
    float* GtS   = (float*)(basep + OFF_GT);
    float* biasS = (float*)(basep + OFF_BIAS);
    float* wi0S  = (float*)(basep + OFF_WI0);
    float* woS   = (float*)(basep + OFF_WO);
    float* boS   = (float*)(basep + OFF_BO);
    float* xS    = (float*)(basep + OFF_X);

    const int tid = threadIdx.x;
    const int bb0 = blockIdx.x * 64;

    // ---- stage small params (all 512 threads) ----
    for (int i = tid; i < 1024; i += 512) biasS[i] = b_ih[i] + b_hh[i];
    for (int i = tid; i < 768;  i += 512) wi0S[i] = W_ih0[i];
    if (tid < 192) woS[tid] = Wo[tid];
    if (tid < 3)   boS[tid] = bo[tid];
    if (tid < 64)  { xS[tid] = 0.5f; xS[64 + tid] = 0.5f; xS[128 + tid] = 0.f; }

    // c-state lives in EPI warps (tid >= 256)
    float cr0[16], cr1[16], cr2[16], cr3[16];
    if (tid >= 256) {
        const int etid = tid - 256;
        const int b = etid & 63, jg = etid >> 6;
        #pragma unroll
        for (int jj = 0; jj < 16; jj++) {
            int j = jg * 16 + jj;
            float hv = g_init[(size_t)(bb0 + b) * 128 + j];
            float cv = g_init[(size_t)(bb0 + b) * 128 + 64 + j];
            cr0[jj] = cv; cr1[jj] = cv; cr2[jj] = cv; cr3[jj] = cv;
            __half bh = __float2half(hv);
            __half bl = __float2half(hv - __half2float(bh));
            #pragma unroll
            for (int l = 0; l < 4; l++) {
                hHiE[(l * 64 + b) * 72 + j] = bh;
                hLoE[(l * 64 + b) * 72 + j] = bl;
            }
        }
    }
    if (tid < 256) {       // prime pipeline: both halves of layer 0
        stageWh(wS, 0, 0, tid);
        stageWh(wS, 0, 1, tid);
    }
    __syncthreads();

    if (tid < 256) {
        // ================= MMA group (warps 0-7) =================
        const int lane = tid & 31, wid = tid >> 5;
        const int m0w = (wid & 1) * 32;
        const int n0w = (wid >> 1) * 32;        // 32 rows within the 128-row half
        const int sel = lane >> 3, lrow = lane & 7;
        const uint32_t a_laneoff = (uint32_t)(((sel & 1) * 8 + lrow) * 144 + (sel >> 1) * 16);
        const uint32_t b_laneoff = (uint32_t)(((sel & 1) * 8 + lrow) * 272 + (sel >> 1) * 16);
        const int gid = lane >> 2, tig = lane & 3;

        for (int t = 0; t < T; t++) {
            for (int l = 0; l < 4; l++) {
                const uint32_t aHi_r = hHiS + (uint32_t)(l * 9216);
                const uint32_t aLo_r = hLoS + (uint32_t)(l * 9216);
                const uint32_t aHi_i = hHiS + (uint32_t)((l - 1) * 9216);
                const uint32_t aLo_i = hLoS + (uint32_t)((l - 1) * 9216);
                const bool last = (t == T - 1 && l == 3);
                const int lnxt = (l + 1) & 3;
                float acc[2][4][4];

                // ---------- half 0 ----------
                cp_wait1();                    // half0(l) resident
                BAR_SYNC(3, 256);
                ACC_ZERO();
                CHUNK2H(aHi_r, aLo_r, 0, wS);                    // recurrent
                BAR_SYNC(2, 512);              // EPI(l-1) done: h[l-1] fresh, Gt free
                if (l > 0) CHUNK2H(aHi_i, aLo_i, 4, wS);         // input
                GT_STORE(0);
                BAR_SYNC(3, 256);              // all warps done reading buffer0
                if (!last) stageWh(wS, lnxt, 0, tid);

                // ---------- half 1 ----------
                cp_wait1();                    // half1(l) resident
                BAR_SYNC(3, 256);
                ACC_ZERO();
                CHUNK2H(aHi_r, aLo_r, 0, wS + W_HALF);
                if (l > 0) CHUNK2H(aHi_i, aLo_i, 4, wS + W_HALF);
                GT_STORE(1);
                BAR_ARRIVE(1, 512);            // full Gt(l) ready -> EPI
                BAR_SYNC(3, 256);              // all warps done reading buffer1
                if (!last) stageWh(wS, lnxt, 1, tid);
            }
        }
    } else {
        // ================= EPI group (warps 8-15) =================
        const int etid = tid - 256;
        const int b = etid & 63, jg = etid >> 6;

        BAR_ARRIVE(2, 512);                 // prime: "EPI(-1) done"
        for (int t = 0; t < T; t++) {
            for (int l = 0; l < 4; l++) {
                BAR_SYNC(1, 512);           // Gt(l) ready
                switch (l) {
                    case 0: EPI(0, cr0); break;
                    case 1: EPI(1, cr1); break;
                    case 2: EPI(2, cr2); break;
                    default: EPI(3, cr3); break;
                }
                if (l == 3) {
                    BAR_SYNC(4, 256);       // h3 visible across EPI warps
                    if (etid < 192) {
                        int jo = etid >> 6;
                        float a = boS[jo];
                        #pragma unroll 8
                        for (int j = 0; j < 64; j++)
                            a += woS[jo * 64 + j] *
                                 (__half2float(hHiE[(192 + b) * 72 + j]) +
                                  __half2float(hLoE[(192 + b) * 72 + j]));
                        out[(size_t)(bb0 + b) * (3 * T) + (size_t)t * 3 + jo] = a;
                        xS[jo * 64 + b] = a;
                    }
                }
                BAR_ARRIVE(2, 512);         // EPI(l) done
            }
        }
    }
}

// ---------------- entry ----------------
extern "C" void kernel_launch(void* const* d_in, const int* in_sizes, int n_in,
                              void* d_out, int out_size) {
    const float* conds     = (const float*)d_in[0];
    const float* W1        = (const float*)d_in[1];
    const float* b1        = (const float*)d_in[2];
    const float* W2        = (const float*)d_in[3];
    const float* b2        = (const float*)d_in[4];
    const float* W_ih0     = (const float*)d_in[5];
    const float* W_ih_rest = (const float*)d_in[6];
    const float* W_hh      = (const float*)d_in[7];
    const float* b_ih      = (const float*)d_in[8];
    const float* b_hh      = (const float*)d_in[9];
    const float* Wo        = (const float*)d_in[10];
    const float* bo        = (const float*)d_in[11];

    int B = in_sizes[0] / 8;
    if (B > B_MAX) B = B_MAX;
    int T = out_size / (B * 3);

    cudaFuncSetAttribute(lstm_main, cudaFuncAttributeMaxDynamicSharedMemorySize, SMEM_REQ);

    repack_k<<<(4 * 256 * 136 + 255) / 256, 256>>>(W_hh, W_ih_rest);
    embed_k<<<B, 128>>>(conds, W1, b1, W2, b2);
    lstm_main<<<B / 64, 512, SMEM_REQ>>>(b_ih, b_hh, W_ih0, Wo, bo, (float*)d_out, T);
}

// round 11
// speedup vs baseline: 1.2630x; 1.2630x over previous
#include <cuda_runtime.h>
#include <cuda_fp16.h>
#include <cstdint>

#define B_MAX 65536

// ---------------- device scratch (no allocs allowed) ----------------
// repacked weights (single fp16 image): [l][n'=4j+gate : 256][k : 136 (128+pad)]
__device__ __align__(16) __half g_wm[4][256][136];
__device__ float g_init[(size_t)B_MAX * 128];   // [b][128] = (h0 | c0)

// ---------------- math ----------------
__device__ __forceinline__ float sigm(float x) { return __fdividef(1.f, 1.f + __expf(-x)); }
__device__ __forceinline__ float tanh_(float x) {
    float ax = fabsf(x);
    float e = __expf(-2.f * ax);
    return copysignf(__fdividef(1.f - e, 1.f + e), x);
}

// ---------------- PTX helpers (portable sm_80+) ----------------
__device__ __forceinline__ uint32_t s32(const void* p) { return (uint32_t)__cvta_generic_to_shared(p); }
__device__ __forceinline__ void cp16(uint32_t dst, const void* src) {
    asm volatile("cp.async.cg.shared.global [%0], [%1], 16;" :: "r"(dst), "l"(src));
}
__device__ __forceinline__ void cp_commit() { asm volatile("cp.async.commit_group;" ::: "memory"); }
__device__ __forceinline__ void cp_wait0()  { asm volatile("cp.async.wait_group 0;" ::: "memory"); }

__device__ __forceinline__ void ldsm4(uint32_t r[4], uint32_t addr) {
    asm volatile("ldmatrix.sync.aligned.m8n8.x4.shared.b16 {%0,%1,%2,%3}, [%4];"
        : "=r"(r[0]), "=r"(r[1]), "=r"(r[2]), "=r"(r[3]) : "r"(addr));
}
__device__ __forceinline__ void mma16816(float d[4], const uint32_t a[4], uint32_t b0, uint32_t b1) {
    asm volatile("mma.sync.aligned.m16n8k16.row.col.f32.f16.f16.f32 "
        "{%0,%1,%2,%3}, {%4,%5,%6,%7}, {%8,%9}, {%0,%1,%2,%3};"
        : "+f"(d[0]), "+f"(d[1]), "+f"(d[2]), "+f"(d[3])
        : "r"(a[0]), "r"(a[1]), "r"(a[2]), "r"(a[3]), "r"(b0), "r"(b1));
}

#define BAR_ARRIVE(id, cnt) asm volatile("bar.arrive %0, %1;" :: "r"(id), "r"(cnt) : "memory")
#define BAR_SYNC(id, cnt)   asm volatile("bar.sync %0, %1;"   :: "r"(id), "r"(cnt) : "memory")

// ---------------- SMEM layout (bytes from 1024-aligned base) ----------------
#define OFF_H    0        // h: [l:4][m:64][k:72] fp16 = 36864 (144B rows)
#define OFF_W    36864    // [256][136] fp16 = 69632 (272B rows)
#define OFF_GT   106496   // Gt[n':256][m:66 pad] f32 = 67584
#define OFF_BIAS 174080   // [4][256] f32 = 4096
#define OFF_WI0  178176   // [256][3] f32 = 3072
#define OFF_WO   181248   // [3][64] f32 = 768
#define OFF_BO   182016   // 16
#define OFF_X    182032   // [3][64] f32 = 768
#define SMEM_USE 182800
#define SMEM_REQ (SMEM_USE + 1024)

// ---------------- prologue 1: weight repack (fp16, gate-interleaved cols) ----------------
__global__ void repack_k(const float* __restrict__ W_hh, const float* __restrict__ W_ih_rest) {
    int idx = blockIdx.x * blockDim.x + threadIdx.x;
    if (idx >= 4 * 256 * 136) return;
    int kc = idx % 136, r = (idx / 136) & 255, l = idx / (136 * 256);
    float v = 0.f;
    if (kc < 128) {
        int j = r >> 2, g = r & 3, n = g * 64 + j;
        if (kc < 64)      v = W_hh[(l * 256 + n) * 64 + kc];
        else if (l > 0)   v = W_ih_rest[((l - 1) * 256 + n) * 64 + (kc - 64)];
    }
    g_wm[l][r][kc] = __float2half(v);
}

// ---------------- prologue 2: decoder_fc -> (h0|c0) ----------------
__global__ void embed_k(const float* __restrict__ conds,
                        const float* __restrict__ W1, const float* __restrict__ b1,
                        const float* __restrict__ W2, const float* __restrict__ b2) {
    int b = blockIdx.x;
    __shared__ float hid[64];
    __shared__ float cnd[8];
    int t = threadIdx.x;  // 128
    if (t < 8) cnd[t] = conds[b * 8 + t];
    __syncthreads();
    if (t < 64) {
        float a = b1[t];
        #pragma unroll
        for (int k = 0; k < 8; k++) a += cnd[k] * W1[t * 8 + k];
        hid[t] = fmaxf(a, 0.f);
    }
    __syncthreads();
    float a = b2[t];
    #pragma unroll
    for (int k = 0; k < 64; k++) a += hid[k] * W2[t * 64 + k];
    g_init[(size_t)b * 128 + t] = a;
}

// stage layer-l weight image into SMEM (69632 B) — MMA threads (tid<256)
__device__ __forceinline__ void stageW(uint32_t wS, int l, int tid) {
    const char* src = (const char*)&g_wm[l][0][0];
    #pragma unroll
    for (int n = 0; n < 17; n++)
        cp16(wS + (uint32_t)(tid * 16 + n * 4096), src + tid * 16 + n * 4096);
    cp_commit();
}

// One K=64 block: single A pass (fp16 h), B fragments per 16-row group.
#define CHUNK1(ABASE, KS0)                                                             \
{                                                                                      \
    _Pragma("unroll")                                                                  \
    for (int ki = 0; ki < 4; ki++) {                                                   \
        uint32_t ah_[2][4];                                                            \
        _Pragma("unroll")                                                              \
        for (int mt = 0; mt < 2; mt++)                                                 \
            ldsm4(ah_[mt], (ABASE) + (uint32_t)((m0w + mt * 16) * 144 + ki * 32) + a_laneoff); \
        _Pragma("unroll")                                                              \
        for (int np = 0; np < 4; np++) {                                               \
            uint32_t bf_[4];                                                           \
            ldsm4(bf_, wS + (uint32_t)((n0w + np * 16) * 272 + ((KS0) + ki) * 32) + b_laneoff); \
            _Pragma("unroll")                                                          \
            for (int mt = 0; mt < 2; mt++) {                                           \
                mma16816(acc[mt][2 * np],     ah_[mt], bf_[0], bf_[2]);                \
                mma16816(acc[mt][2 * np + 1], ah_[mt], bf_[1], bf_[3]);                \
            }                                                                          \
        }                                                                              \
    }                                                                                  \
}

// epilogue for layer L with c-register array CR (EPI threads: b, jg)
#define EPI(L, CR)                                                                     \
{                                                                                      \
    float x0 = 0.f, x1 = 0.f, x2 = 0.f;                                                \
    if ((L) == 0) { x0 = xS[b]; x1 = xS[64 + b]; x2 = xS[128 + b]; }                   \
    _Pragma("unroll")                                                                  \
    for (int jj = 0; jj < 16; jj++) {                                                  \
        int j = jg * 16 + jj;                                                          \
        float vi = GtS[(4 * j + 0) * 66 + b] + biasS[(L) * 256 + j];                   \
        float vf = GtS[(4 * j + 1) * 66 + b] + biasS[(L) * 256 + 64 + j];              \
        float vg = GtS[(4 * j + 2) * 66 + b] + biasS[(L) * 256 + 128 + j];             \
        float vo = GtS[(4 * j + 3) * 66 + b] + biasS[(L) * 256 + 192 + j];             \
        if ((L) == 0) {                                                                \
            vi += x0 * wi0S[j * 3] + x1 * wi0S[j * 3 + 1] + x2 * wi0S[j * 3 + 2];      \
            vf += x0 * wi0S[(64 + j) * 3] + x1 * wi0S[(64 + j) * 3 + 1] + x2 * wi0S[(64 + j) * 3 + 2];   \
            vg += x0 * wi0S[(128 + j) * 3] + x1 * wi0S[(128 + j) * 3 + 1] + x2 * wi0S[(128 + j) * 3 + 2]; \
            vo += x0 * wi0S[(192 + j) * 3] + x1 * wi0S[(192 + j) * 3 + 1] + x2 * wi0S[(192 + j) * 3 + 2]; \
        }                                                                              \
        float cn = sigm(vf) * CR[jj] + sigm(vi) * tanh_(vg);                           \
        CR[jj] = cn;                                                                   \
        float hn = sigm(vo) * tanh_(cn);                                               \
        hE[((L) * 64 + b) * 72 + j] = __float2half(hn);                                \
    }                                                                                  \
}

__global__ __launch_bounds__(512, 1)
void lstm_main(const float* __restrict__ b_ih, const float* __restrict__ b_hh,
               const float* __restrict__ W_ih0,
               const float* __restrict__ Wo, const float* __restrict__ bo,
               float* __restrict__ out, int T) {
    extern __shared__ char raw[];
    char* basep = (char*)(((uintptr_t)raw + 1023) & ~(uintptr_t)1023);
    const uint32_t hS = s32(basep + OFF_H);
    const uint32_t wS = s32(basep + OFF_W);
    __half* hE   = (__half*)(basep + OFF_H);
    float* GtS   = (float*)(basep + OFF_GT);
    float* biasS = (float*)(basep + OFF_BIAS);
    float* wi0S  = (float*)(basep + OFF_WI0);
    float* woS   = (float*)(basep + OFF_WO);
    float* boS   = (float*)(basep + OFF_BO);
    float* xS    = (float*)(basep + OFF_X);

    const int tid = threadIdx.x;
    const int bb0 = blockIdx.x * 64;

    // ---- stage small params (all 512 threads) ----
    for (int i = tid; i < 1024; i += 512) biasS[i] = b_ih[i] + b_hh[i];
    for (int i = tid; i < 768;  i += 512) wi0S[i] = W_ih0[i];
    if (tid < 192) woS[tid] = Wo[tid];
    if (tid < 3)   boS[tid] = bo[tid];
    if (tid < 64)  { xS[tid] = 0.5f; xS[64 + tid] = 0.5f; xS[128 + tid] = 0.f; }

    // c-state lives in EPI warps (tid >= 256)
    float cr0[16], cr1[16], cr2[16], cr3[16];
    if (tid >= 256) {
        const int etid = tid - 256;
        const int b = etid & 63, jg = etid >> 6;
        #pragma unroll
        for (int jj = 0; jj < 16; jj++) {
            int j = jg * 16 + jj;
            float hv = g_init[(size_t)(bb0 + b) * 128 + j];
            float cv = g_init[(size_t)(bb0 + b) * 128 + 64 + j];
            cr0[jj] = cv; cr1[jj] = cv; cr2[jj] = cv; cr3[jj] = cv;
            __half bh = __float2half(hv);
            #pragma unroll
            for (int l = 0; l < 4; l++) hE[(l * 64 + b) * 72 + j] = bh;
        }
    }
    if (tid < 256) stageW(wS, 0, tid);   // prefetch W(layer 0)
    __syncthreads();

    if (tid < 256) {
        // ================= MMA group (warps 0-7) =================
        const int lane = tid & 31, wid = tid >> 5;
        const int m0w = (wid & 1) * 32;
        const int n0w = (wid >> 1) * 64;
        const int sel = lane >> 3, lrow = lane & 7;
        const uint32_t a_laneoff = (uint32_t)(((sel & 1) * 8 + lrow) * 144 + (sel >> 1) * 16);
        const uint32_t b_laneoff = (uint32_t)(((sel & 1) * 8 + lrow) * 272 + (sel >> 1) * 16);
        const int gid = lane >> 2, tig = lane & 3;

        for (int t = 0; t < T; t++) {
            for (int l = 0; l < 4; l++) {
                cp_wait0();
                BAR_SYNC(3, 256);           // W(l) fully staged (all MMA warps)

                float acc[2][8][4];
                #pragma unroll
                for (int mt = 0; mt < 2; mt++)
                    #pragma unroll
                    for (int nt = 0; nt < 8; nt++)
                        #pragma unroll
                        for (int q = 0; q < 4; q++) acc[mt][nt][q] = 0.f;

                // recurrent half: A = h[l] (t-1) — independent of EPI(l-1)
                CHUNK1(hS + (uint32_t)(l * 9216), 0);

                BAR_SYNC(2, 512);           // EPI(l-1) done: h[l-1] fresh, Gt free

                // input half: A = h[l-1] (fresh)
                if (l > 0)
                    CHUNK1(hS + (uint32_t)((l - 1) * 9216), 4);

                // write gate pre-activations, transposed: Gt[n'][m]
                #pragma unroll
                for (int mt = 0; mt < 2; mt++)
                    #pragma unroll
                    for (int nt = 0; nt < 8; nt++) {
                        int col = n0w + nt * 8 + 2 * tig;
                        int row = m0w + mt * 16 + gid;
                        GtS[col * 66 + row]           = acc[mt][nt][0];
                        GtS[(col + 1) * 66 + row]     = acc[mt][nt][1];
                        GtS[col * 66 + row + 8]       = acc[mt][nt][2];
                        GtS[(col + 1) * 66 + row + 8] = acc[mt][nt][3];
                    }
                BAR_ARRIVE(1, 512);         // Gt(l) ready -> EPI

                BAR_SYNC(3, 256);           // all MMA warps done reading W(l)
                if (!(t == T - 1 && l == 3)) stageW(wS, (l + 1) & 3, tid);
            }
        }
    } else {
        // ================= EPI group (warps 8-15) =================
        const int etid = tid - 256;
        const int b = etid & 63, jg = etid >> 6;

        BAR_ARRIVE(2, 512);                 // prime: "EPI(-1) done"
        for (int t = 0; t < T; t++) {
            for (int l = 0; l < 4; l++) {
                BAR_SYNC(1, 512);           // Gt(l) ready
                switch (l) {
                    case 0: EPI(0, cr0); break;
                    case 1: EPI(1, cr1); break;
                    case 2: EPI(2, cr2); break;
                    default: EPI(3, cr3); break;
                }
                if (l == 3) {
                    BAR_SYNC(4, 256);       // h3 visible across EPI warps
                    if (etid < 192) {
                        int jo = etid >> 6;
                        float a = boS[jo];
                        #pragma unroll 8
                        for (int j = 0; j < 64; j++)
                            a += woS[jo * 64 + j] * __half2float(hE[(192 + b) * 72 + j]);
                        out[(size_t)(bb0 + b) * (3 * T) + (size_t)t * 3 + jo] = a;
                        xS[jo * 64 + b] = a;
                    }
                }
                BAR_ARRIVE(2, 512);         // EPI(l) done
            }
        }
    }
}

// ---------------- entry ----------------
extern "C" void kernel_launch(void* const* d_in, const int* in_sizes, int n_in,
                              void* d_out, int out_size) {
    const float* conds     = (const float*)d_in[0];
    const float* W1        = (const float*)d_in[1];
    const float* b1        = (const float*)d_in[2];
    const float* W2        = (const float*)d_in[3];
    const float* b2        = (const float*)d_in[4];
    const float* W_ih0     = (const float*)d_in[5];
    const float* W_ih_rest = (const float*)d_in[6];
    const float* W_hh      = (const float*)d_in[7];
    const float* b_ih      = (const float*)d_in[8];
    const float* b_hh      = (const float*)d_in[9];
    const float* Wo        = (const float*)d_in[10];
    const float* bo        = (const float*)d_in[11];

    int B = in_sizes[0] / 8;
    if (B > B_MAX) B = B_MAX;
    int T = out_size / (B * 3);

    cudaFuncSetAttribute(lstm_main, cudaFuncAttributeMaxDynamicSharedMemorySize, SMEM_REQ);

    repack_k<<<(4 * 256 * 136 + 255) / 256, 256>>>(W_hh, W_ih_rest);
    embed_k<<<B, 128>>>(conds, W1, b1, W2, b2);
    lstm_main<<<B / 64, 512, SMEM_REQ>>>(b_ih, b_hh, W_ih0, Wo, bo, (float*)d_out, T);
}

// round 12
// speedup vs baseline: 1.4484x; 1.1468x over previous
#include <cuda_runtime.h>
#include <cuda_fp16.h>
#include <cstdint>

#define B_MAX 65536

// ---------------- device scratch (no allocs allowed) ----------------
// repacked weights (single fp16 image): [l][n'=4j+gate : 256][k : 136 (128+pad)]
__device__ __align__(16) __half g_wm[4][256][136];
__device__ float g_init[(size_t)B_MAX * 128];   // [b][128] = (h0 | c0)

// ---------------- math (HW tanh; sigmoid via tanh identity) ----------------
__device__ __forceinline__ float tanh_(float x) {
    float y; asm("tanh.approx.f32 %0, %1;" : "=f"(y) : "f"(x)); return y;
}
__device__ __forceinline__ float sigm(float x) {
    return fmaf(tanh_(0.5f * x), 0.5f, 0.5f);
}

// ---------------- PTX helpers (portable sm_80+) ----------------
__device__ __forceinline__ uint32_t s32(const void* p) { return (uint32_t)__cvta_generic_to_shared(p); }
__device__ __forceinline__ void cp16(uint32_t dst, const void* src) {
    asm volatile("cp.async.cg.shared.global [%0], [%1], 16;" :: "r"(dst), "l"(src));
}
__device__ __forceinline__ void cp_commit() { asm volatile("cp.async.commit_group;" ::: "memory"); }
__device__ __forceinline__ void cp_wait0()  { asm volatile("cp.async.wait_group 0;" ::: "memory"); }

__device__ __forceinline__ void ldsm4(uint32_t r[4], uint32_t addr) {
    asm volatile("ldmatrix.sync.aligned.m8n8.x4.shared.b16 {%0,%1,%2,%3}, [%4];"
        : "=r"(r[0]), "=r"(r[1]), "=r"(r[2]), "=r"(r[3]) : "r"(addr));
}
__device__ __forceinline__ void mma16816(float d[4], const uint32_t a[4], uint32_t b0, uint32_t b1) {
    asm volatile("mma.sync.aligned.m16n8k16.row.col.f32.f16.f16.f32 "
        "{%0,%1,%2,%3}, {%4,%5,%6,%7}, {%8,%9}, {%0,%1,%2,%3};"
        : "+f"(d[0]), "+f"(d[1]), "+f"(d[2]), "+f"(d[3])
        : "r"(a[0]), "r"(a[1]), "r"(a[2]), "r"(a[3]), "r"(b0), "r"(b1));
}

#define BAR_ARRIVE(id, cnt) asm volatile("bar.arrive %0, %1;" :: "r"(id), "r"(cnt) : "memory")
#define BAR_SYNC(id, cnt)   asm volatile("bar.sync %0, %1;"   :: "r"(id), "r"(cnt) : "memory")

// ---------------- SMEM layout (bytes from 1024-aligned base) ----------------
#define OFF_H    0        // h: [l:4][m:64][k:72] fp16 = 36864 (144B rows)
#define OFF_W    36864    // [256][136] fp16 = 69632 (272B rows)
#define OFF_GT   106496   // Gt[n':256][m:66 pad] f32 = 67584
#define OFF_BIAS 174080   // [4][256] f32 = 4096
#define OFF_WI0  178176   // [256][3] f32 = 3072
#define OFF_WO   181248   // [3][64] f32 = 768
#define OFF_BO   182016   // 16
#define OFF_X    182032   // [3][64] f32 = 768
#define SMEM_USE 182800
#define SMEM_REQ (SMEM_USE + 1024)

// ---------------- single prologue: weight repack + decoder_fc ----------------
// grid = B blocks x 128 threads. Every block does the embed for batch row
// blockIdx.x; blocks 0..1087 additionally repack one 128-element slice of W.
__global__ void prologue_k(const float* __restrict__ conds,
                           const float* __restrict__ W1, const float* __restrict__ b1,
                           const float* __restrict__ W2, const float* __restrict__ b2,
                           const float* __restrict__ W_hh, const float* __restrict__ W_ih_rest) {
    const int b = blockIdx.x;
    const int t = threadIdx.x;  // 128

    // ---- repack slice (blocks 0..1087) ----
    int idx = b * 128 + t;
    if (idx < 4 * 256 * 136) {
        int kc = idx % 136, r = (idx / 136) & 255, l = idx / (136 * 256);
        float v = 0.f;
        if (kc < 128) {
            int j = r >> 2, g = r & 3, n = g * 64 + j;
            if (kc < 64)      v = W_hh[(l * 256 + n) * 64 + kc];
            else if (l > 0)   v = W_ih_rest[((l - 1) * 256 + n) * 64 + (kc - 64)];
        }
        g_wm[l][r][kc] = __float2half(v);
    }

    // ---- embed for batch row b ----
    __shared__ float hid[64];
    __shared__ float cnd[8];
    if (t < 8) cnd[t] = conds[b * 8 + t];
    __syncthreads();
    if (t < 64) {
        float a = b1[t];
        #pragma unroll
        for (int k = 0; k < 8; k++) a += cnd[k] * W1[t * 8 + k];
        hid[t] = fmaxf(a, 0.f);
    }
    __syncthreads();
    float a = b2[t];
    #pragma unroll
    for (int k = 0; k < 64; k++) a += hid[k] * W2[t * 64 + k];
    g_init[(size_t)b * 128 + t] = a;
}

// stage layer-l weight image into SMEM (69632 B) — MMA threads (tid<256)
__device__ __forceinline__ void stageW(uint32_t wS, int l, int tid) {
    const char* src = (const char*)&g_wm[l][0][0];
    #pragma unroll
    for (int n = 0; n < 17; n++)
        cp16(wS + (uint32_t)(tid * 16 + n * 4096), src + tid * 16 + n * 4096);
    cp_commit();
}

// One K=64 block: single A pass (fp16 h), B fragments per 16-row group.
#define CHUNK1(ABASE, KS0)                                                             \
{                                                                                      \
    _Pragma("unroll")                                                                  \
    for (int ki = 0; ki < 4; ki++) {                                                   \
        uint32_t ah_[2][4];                                                            \
        _Pragma("unroll")                                                              \
        for (int mt = 0; mt < 2; mt++)                                                 \
            ldsm4(ah_[mt], (ABASE) + (uint32_t)((m0w + mt * 16) * 144 + ki * 32) + a_laneoff); \
        _Pragma("unroll")                                                              \
        for (int np = 0; np < 4; np++) {                                               \
            uint32_t bf_[4];                                                           \
            ldsm4(bf_, wS + (uint32_t)((n0w + np * 16) * 272 + ((KS0) + ki) * 32) + b_laneoff); \
            _Pragma("unroll")                                                          \
            for (int mt = 0; mt < 2; mt++) {                                           \
                mma16816(acc[mt][2 * np],     ah_[mt], bf_[0], bf_[2]);                \
                mma16816(acc[mt][2 * np + 1], ah_[mt], bf_[1], bf_[3]);                \
            }                                                                          \
        }                                                                              \
    }                                                                                  \
}

// epilogue for layer L with c-register array CR (EPI threads: b, jg)
#define EPI(L, CR)                                                                     \
{                                                                                      \
    float x0 = 0.f, x1 = 0.f, x2 = 0.f;                                                \
    if ((L) == 0) { x0 = xS[b]; x1 = xS[64 + b]; x2 = xS[128 + b]; }                   \
    _Pragma("unroll")                                                                  \
    for (int jj = 0; jj < 16; jj++) {                                                  \
        int j = jg * 16 + jj;                                                          \
        float vi = GtS[(4 * j + 0) * 66 + b] + biasS[(L) * 256 + j];                   \
        float vf = GtS[(4 * j + 1) * 66 + b] + biasS[(L) * 256 + 64 + j];              \
        float vg = GtS[(4 * j + 2) * 66 + b] + biasS[(L) * 256 + 128 + j];             \
        float vo = GtS[(4 * j + 3) * 66 + b] + biasS[(L) * 256 + 192 + j];             \
        if ((L) == 0) {                                                                \
            vi += x0 * wi0S[j * 3] + x1 * wi0S[j * 3 + 1] + x2 * wi0S[j * 3 + 2];      \
            vf += x0 * wi0S[(64 + j) * 3] + x1 * wi0S[(64 + j) * 3 + 1] + x2 * wi0S[(64 + j) * 3 + 2];   \
            vg += x0 * wi0S[(128 + j) * 3] + x1 * wi0S[(128 + j) * 3 + 1] + x2 * wi0S[(128 + j) * 3 + 2]; \
            vo += x0 * wi0S[(192 + j) * 3] + x1 * wi0S[(192 + j) * 3 + 1] + x2 * wi0S[(192 + j) * 3 + 2]; \
        }                                                                              \
        float cn = sigm(vf) * CR[jj] + sigm(vi) * tanh_(vg);                           \
        CR[jj] = cn;                                                                   \
        float hn = sigm(vo) * tanh_(cn);                                               \
        hE[((L) * 64 + b) * 72 + j] = __float2half(hn);                                \
    }                                                                                  \
}

__global__ __launch_bounds__(512, 1)
void lstm_main(const float* __restrict__ b_ih, const float* __restrict__ b_hh,
               const float* __restrict__ W_ih0,
               const float* __restrict__ Wo, const float* __restrict__ bo,
               float* __restrict__ out, int T) {
    extern __shared__ char raw[];
    char* basep = (char*)(((uintptr_t)raw + 1023) & ~(uintptr_t)1023);
    const uint32_t hS = s32(basep + OFF_H);
    const uint32_t wS = s32(basep + OFF_W);
    __half* hE   = (__half*)(basep + OFF_H);
    float* GtS   = (float*)(basep + OFF_GT);
    float* biasS = (float*)(basep + OFF_BIAS);
    float* wi0S  = (float*)(basep + OFF_WI0);
    float* woS   = (float*)(basep + OFF_WO);
    float* boS   = (float*)(basep + OFF_BO);
    float* xS    = (float*)(basep + OFF_X);

    const int tid = threadIdx.x;
    const int bb0 = blockIdx.x * 64;

    // ---- stage small params (all 512 threads) ----
    for (int i = tid; i < 1024; i += 512) biasS[i] = b_ih[i] + b_hh[i];
    for (int i = tid; i < 768;  i += 512) wi0S[i] = W_ih0[i];
    if (tid < 192) woS[tid] = Wo[tid];
    if (tid < 3)   boS[tid] = bo[tid];
    if (tid < 64)  { xS[tid] = 0.5f; xS[64 + tid] = 0.5f; xS[128 + tid] = 0.f; }

    // c-state lives in EPI warps (tid >= 256)
    float cr0[16], cr1[16], cr2[16], cr3[16];
    if (tid >= 256) {
        const int etid = tid - 256;
        const int b = etid & 63, jg = etid >> 6;
        #pragma unroll
        for (int jj = 0; jj < 16; jj++) {
            int j = jg * 16 + jj;
            float hv = g_init[(size_t)(bb0 + b) * 128 + j];
            float cv = g_init[(size_t)(bb0 + b) * 128 + 64 + j];
            cr0[jj] = cv; cr1[jj] = cv; cr2[jj] = cv; cr3[jj] = cv;
            __half bh = __float2half(hv);
            #pragma unroll
            for (int l = 0; l < 4; l++) hE[(l * 64 + b) * 72 + j] = bh;
        }
    }
    if (tid < 256) stageW(wS, 0, tid);   // prefetch W(layer 0)
    __syncthreads();

    if (tid < 256) {
        // ================= MMA group (warps 0-7) =================
        const int lane = tid & 31, wid = tid >> 5;
        const int m0w = (wid & 1) * 32;
        const int n0w = (wid >> 1) * 64;
        const int sel = lane >> 3, lrow = lane & 7;
        const uint32_t a_laneoff = (uint32_t)(((sel & 1) * 8 + lrow) * 144 + (sel >> 1) * 16);
        const uint32_t b_laneoff = (uint32_t)(((sel & 1) * 8 + lrow) * 272 + (sel >> 1) * 16);
        const int gid = lane >> 2, tig = lane & 3;

        for (int t = 0; t < T; t++) {
            for (int l = 0; l < 4; l++) {
                cp_wait0();
                BAR_SYNC(3, 256);           // W(l) fully staged (all MMA warps)

                float acc[2][8][4];
                #pragma unroll
                for (int mt = 0; mt < 2; mt++)
                    #pragma unroll
                    for (int nt = 0; nt < 8; nt++)
                        #pragma unroll
                        for (int q = 0; q < 4; q++) acc[mt][nt][q] = 0.f;

                // recurrent half: A = h[l] (t-1) — independent of EPI(l-1)
                CHUNK1(hS + (uint32_t)(l * 9216), 0);

                BAR_SYNC(2, 512);           // EPI(l-1) done: h[l-1] fresh, Gt free

                // input half: A = h[l-1] (fresh)
                if (l > 0)
                    CHUNK1(hS + (uint32_t)((l - 1) * 9216), 4);

                // write gate pre-activations, transposed: Gt[n'][m]
                #pragma unroll
                for (int mt = 0; mt < 2; mt++)
                    #pragma unroll
                    for (int nt = 0; nt < 8; nt++) {
                        int col = n0w + nt * 8 + 2 * tig;
                        int row = m0w + mt * 16 + gid;
                        GtS[col * 66 + row]           = acc[mt][nt][0];
                        GtS[(col + 1) * 66 + row]     = acc[mt][nt][1];
                        GtS[col * 66 + row + 8]       = acc[mt][nt][2];
                        GtS[(col + 1) * 66 + row + 8] = acc[mt][nt][3];
                    }
                BAR_ARRIVE(1, 512);         // Gt(l) ready -> EPI

                BAR_SYNC(3, 256);           // all MMA warps done reading W(l)
                if (!(t == T - 1 && l == 3)) stageW(wS, (l + 1) & 3, tid);
            }
        }
    } else {
        // ================= EPI group (warps 8-15) =================
        const int etid = tid - 256;
        const int b = etid & 63, jg = etid >> 6;

        BAR_ARRIVE(2, 512);                 // prime: "EPI(-1) done"
        for (int t = 0; t < T; t++) {
            for (int l = 0; l < 4; l++) {
                BAR_SYNC(1, 512);           // Gt(l) ready
                switch (l) {
                    case 0: EPI(0, cr0); break;
                    case 1: EPI(1, cr1); break;
                    case 2: EPI(2, cr2); break;
                    default: EPI(3, cr3); break;
                }
                if (l == 3) {
                    BAR_SYNC(4, 256);       // h3 visible across EPI warps
                    if (etid < 192) {
                        int jo = etid >> 6;
                        float a = boS[jo];
                        #pragma unroll 8
                        for (int j = 0; j < 64; j++)
                            a += woS[jo * 64 + j] * __half2float(hE[(192 + b) * 72 + j]);
                        out[(size_t)(bb0 + b) * (3 * T) + (size_t)t * 3 + jo] = a;
                        xS[jo * 64 + b] = a;
                    }
                }
                BAR_ARRIVE(2, 512);         // EPI(l) done
            }
        }
    }
}

// ---------------- entry ----------------
extern "C" void kernel_launch(void* const* d_in, const int* in_sizes, int n_in,
                              void* d_out, int out_size) {
    const float* conds     = (const float*)d_in[0];
    const float* W1        = (const float*)d_in[1];
    const float* b1        = (const float*)d_in[2];
    const float* W2        = (const float*)d_in[3];
    const float* b2        = (const float*)d_in[4];
    const float* W_ih0     = (const float*)d_in[5];
    const float* W_ih_rest = (const float*)d_in[6];
    const float* W_hh      = (const float*)d_in[7];
    const float* b_ih      = (const float*)d_in[8];
    const float* b_hh      = (const float*)d_in[9];
    const float* Wo        = (const float*)d_in[10];
    const float* bo        = (const float*)d_in[11];

    int B = in_sizes[0] / 8;
    if (B > B_MAX) B = B_MAX;
    int T = out_size / (B * 3);

    cudaFuncSetAttribute(lstm_main, cudaFuncAttributeMaxDynamicSharedMemorySize, SMEM_REQ);

    prologue_k<<<B, 128>>>(conds, W1, b1, W2, b2, W_hh, W_ih_rest);
    lstm_main<<<B / 64, 512, SMEM_REQ>>>(b_ih, b_hh, W_ih0, Wo, bo, (float*)d_out, T);
}

// round 13
// speedup vs baseline: 1.7472x; 1.2063x over previous
#include <cuda_runtime.h>
#include <cuda_fp16.h>
#include <cstdint>

#define B_MAX 65536

// ---------------- device scratch (no allocs allowed) ----------------
// repacked weights (single fp16 image): [l][n'=4j+gate : 256][k : 136 (128+pad)]
__device__ __align__(16) __half g_wm[4][256][136];
__device__ float g_init[(size_t)B_MAX * 128];   // [b][128] = (h0 | c0)

// ---------------- math (HW tanh; sigmoid via tanh identity) ----------------
__device__ __forceinline__ float tanh_(float x) {
    float y; asm("tanh.approx.f32 %0, %1;" : "=f"(y) : "f"(x)); return y;
}
__device__ __forceinline__ float sigm(float x) {
    return fmaf(tanh_(0.5f * x), 0.5f, 0.5f);
}

// ---------------- PTX helpers (portable sm_80+) ----------------
__device__ __forceinline__ uint32_t s32(const void* p) { return (uint32_t)__cvta_generic_to_shared(p); }
__device__ __forceinline__ void cp16(uint32_t dst, const void* src) {
    asm volatile("cp.async.cg.shared.global [%0], [%1], 16;" :: "r"(dst), "l"(src));
}
__device__ __forceinline__ void cp_commit() { asm volatile("cp.async.commit_group;" ::: "memory"); }
__device__ __forceinline__ void cp_wait0()  { asm volatile("cp.async.wait_group 0;" ::: "memory"); }

__device__ __forceinline__ void ldsm4(uint32_t r[4], uint32_t addr) {
    asm volatile("ldmatrix.sync.aligned.m8n8.x4.shared.b16 {%0,%1,%2,%3}, [%4];"
        : "=r"(r[0]), "=r"(r[1]), "=r"(r[2]), "=r"(r[3]) : "r"(addr));
}
__device__ __forceinline__ void mma16816(float d[4], const uint32_t a[4], uint32_t b0, uint32_t b1) {
    asm volatile("mma.sync.aligned.m16n8k16.row.col.f32.f16.f16.f32 "
        "{%0,%1,%2,%3}, {%4,%5,%6,%7}, {%8,%9}, {%0,%1,%2,%3};"
        : "+f"(d[0]), "+f"(d[1]), "+f"(d[2]), "+f"(d[3])
        : "r"(a[0]), "r"(a[1]), "r"(a[2]), "r"(a[3]), "r"(b0), "r"(b1));
}
__device__ __forceinline__ void sts64(uint32_t addr, float a, float b) {
    asm volatile("st.shared.v2.f32 [%0], {%1,%2};" :: "r"(addr), "f"(a), "f"(b) : "memory");
}
__device__ __forceinline__ void lds128(float4& v, uint32_t addr) {
    asm volatile("ld.shared.v4.f32 {%0,%1,%2,%3}, [%4];"
        : "=f"(v.x), "=f"(v.y), "=f"(v.z), "=f"(v.w) : "r"(addr));
}
__device__ __forceinline__ void sts128(uint32_t addr, const uint32_t r[4]) {
    asm volatile("st.shared.v4.b32 [%0], {%1,%2,%3,%4};"
        :: "r"(addr), "r"(r[0]), "r"(r[1]), "r"(r[2]), "r"(r[3]) : "memory");
}

#define BAR_ARRIVE(id, cnt) asm volatile("bar.arrive %0, %1;" :: "r"(id), "r"(cnt) : "memory")
#define BAR_SYNC(id, cnt)   asm volatile("bar.sync %0, %1;"   :: "r"(id), "r"(cnt) : "memory")

// ---------------- SMEM layout (bytes from 1024-aligned base) ----------------
// Gt2: [j:64][b:64][gate:4] f32, j-stride 272 words (1088 B, ≡16 mod 32 banks)
#define GT_JS 272
#define OFF_H    0        // h: [l:4][m:64][k:72] fp16 = 36864 (144B rows)
#define OFF_W    36864    // [256][136] fp16 = 69632 (272B rows)
#define OFF_GT   106496   // 64*272*4 = 69632
#define OFF_BIAS 176128   // [4][256] f32 (n'=4j+g order) = 4096
#define OFF_WI0  180224   // [256][3] f32 = 3072
#define OFF_WO   183296   // [3][64] f32 = 768
#define OFF_BO   184064   // 16
#define OFF_X    184080   // [3][64] f32 = 768
#define SMEM_USE 184848
#define SMEM_REQ (SMEM_USE + 1024)

// ---------------- single prologue: weight repack + decoder_fc ----------------
__global__ void prologue_k(const float* __restrict__ conds,
                           const float* __restrict__ W1, const float* __restrict__ b1,
                           const float* __restrict__ W2, const float* __restrict__ b2,
                           const float* __restrict__ W_hh, const float* __restrict__ W_ih_rest) {
    const int b = blockIdx.x;
    const int t = threadIdx.x;  // 128

    // ---- repack slice (blocks 0..1087) ----
    int idx = b * 128 + t;
    if (idx < 4 * 256 * 136) {
        int kc = idx % 136, r = (idx / 136) & 255, l = idx / (136 * 256);
        float v = 0.f;
        if (kc < 128) {
            int j = r >> 2, g = r & 3, n = g * 64 + j;
            if (kc < 64)      v = W_hh[(l * 256 + n) * 64 + kc];
            else if (l > 0)   v = W_ih_rest[((l - 1) * 256 + n) * 64 + (kc - 64)];
        }
        g_wm[l][r][kc] = __float2half(v);
    }

    // ---- embed for batch row b ----
    __shared__ float hid[64];
    __shared__ float cnd[8];
    if (t < 8) cnd[t] = conds[b * 8 + t];
    __syncthreads();
    if (t < 64) {
        float a = b1[t];
        #pragma unroll
        for (int k = 0; k < 8; k++) a += cnd[k] * W1[t * 8 + k];
        hid[t] = fmaxf(a, 0.f);
    }
    __syncthreads();
    float a = b2[t];
    #pragma unroll
    for (int k = 0; k < 64; k++) a += hid[k] * W2[t * 64 + k];
    g_init[(size_t)b * 128 + t] = a;
}

// stage layer-l weight image into SMEM (69632 B) — MMA threads (tid<256)
__device__ __forceinline__ void stageW(uint32_t wS, int l, int tid) {
    const char* src = (const char*)&g_wm[l][0][0];
    #pragma unroll
    for (int n = 0; n < 17; n++)
        cp16(wS + (uint32_t)(tid * 16 + n * 4096), src + tid * 16 + n * 4096);
    cp_commit();
}

// One K=64 block: single A pass (fp16 h), B fragments per 16-row group.
#define CHUNK1(ABASE, KS0)                                                             \
{                                                                                      \
    _Pragma("unroll")                                                                  \
    for (int ki = 0; ki < 4; ki++) {                                                   \
        uint32_t ah_[2][4];                                                            \
        _Pragma("unroll")                                                              \
        for (int mt = 0; mt < 2; mt++)                                                 \
            ldsm4(ah_[mt], (ABASE) + (uint32_t)((m0w + mt * 16) * 144 + ki * 32) + a_laneoff); \
        _Pragma("unroll")                                                              \
        for (int np = 0; np < 4; np++) {                                               \
            uint32_t bf_[4];                                                           \
            ldsm4(bf_, wS + (uint32_t)((n0w + np * 16) * 272 + ((KS0) + ki) * 32) + b_laneoff); \
            _Pragma("unroll")                                                          \
            for (int mt = 0; mt < 2; mt++) {                                           \
                mma16816(acc[mt][2 * np],     ah_[mt], bf_[0], bf_[2]);                \
                mma16816(acc[mt][2 * np + 1], ah_[mt], bf_[1], bf_[3]);                \
            }                                                                          \
        }                                                                              \
    }                                                                                  \
}

// epilogue for layer L with c-register array CR (EPI threads: b, jg)
// Gt2 float4 = (i,f,g,o) preactivations incl. bias.
#define EPI(L, CR)                                                                     \
{                                                                                      \
    float x0 = 0.f, x1 = 0.f, x2 = 0.f;                                                \
    if ((L) == 0) { x0 = xS[b]; x1 = xS[64 + b]; x2 = xS[128 + b]; }                   \
    uint32_t hh[8];                                                                    \
    _Pragma("unroll")                                                                  \
    for (int jj = 0; jj < 16; jj++) {                                                  \
        int j = jg * 16 + jj;                                                          \
        float4 gv;                                                                     \
        lds128(gv, gtS + (uint32_t)((j * GT_JS + b * 4) * 4));                         \
        float vi = gv.x, vf = gv.y, vg = gv.z, vo = gv.w;                              \
        if ((L) == 0) {                                                                \
            vi += x0 * wi0S[j * 3] + x1 * wi0S[j * 3 + 1] + x2 * wi0S[j * 3 + 2];      \
            vf += x0 * wi0S[(64 + j) * 3] + x1 * wi0S[(64 + j) * 3 + 1] + x2 * wi0S[(64 + j) * 3 + 2];   \
            vg += x0 * wi0S[(128 + j) * 3] + x1 * wi0S[(128 + j) * 3 + 1] + x2 * wi0S[(128 + j) * 3 + 2]; \
            vo += x0 * wi0S[(192 + j) * 3] + x1 * wi0S[(192 + j) * 3 + 1] + x2 * wi0S[(192 + j) * 3 + 2]; \
        }                                                                              \
        float cn = sigm(vf) * CR[jj] + sigm(vi) * tanh_(vg);                           \
        CR[jj] = cn;                                                                   \
        float hn = sigm(vo) * tanh_(cn);                                               \
        uint32_t hu = (uint32_t)__half_as_ushort(__float2half(hn));                    \
        if (jj & 1) hh[jj >> 1] |= hu << 16; else hh[jj >> 1] = hu;                    \
    }                                                                                  \
    uint32_t hdst = hS + (uint32_t)(((L) * 64 + b) * 144 + jg * 32);                   \
    sts128(hdst, hh);                                                                  \
    sts128(hdst + 16, hh + 4);                                                         \
}

__global__ __launch_bounds__(512, 1)
void lstm_main(const float* __restrict__ b_ih, const float* __restrict__ b_hh,
               const float* __restrict__ W_ih0,
               const float* __restrict__ Wo, const float* __restrict__ bo,
               float* __restrict__ out, int T) {
    extern __shared__ char raw[];
    char* basep = (char*)(((uintptr_t)raw + 1023) & ~(uintptr_t)1023);
    const uint32_t hS  = s32(basep + OFF_H);
    const uint32_t wS  = s32(basep + OFF_W);
    const uint32_t gtS = s32(basep + OFF_GT);
    __half* hE   = (__half*)(basep + OFF_H);
    float* biasS = (float*)(basep + OFF_BIAS);
    float* wi0S  = (float*)(basep + OFF_WI0);
    float* woS   = (float*)(basep + OFF_WO);
    float* boS   = (float*)(basep + OFF_BO);
    float* xS    = (float*)(basep + OFF_X);

    const int tid = threadIdx.x;
    const int bb0 = blockIdx.x * 64;

    // ---- stage small params (all 512 threads) ----
    // bias permuted to n' = 4j+g order to match MMA columns
    for (int i = tid; i < 1024; i += 512) {
        int l = i >> 8, n = i & 255, g = n >> 6, j = n & 63;
        biasS[l * 256 + 4 * j + g] = b_ih[i] + b_hh[i];
    }
    for (int i = tid; i < 768;  i += 512) wi0S[i] = W_ih0[i];
    if (tid < 192) woS[tid] = Wo[tid];
    if (tid < 3)   boS[tid] = bo[tid];
    if (tid < 64)  { xS[tid] = 0.5f; xS[64 + tid] = 0.5f; xS[128 + tid] = 0.f; }

    // c-state lives in EPI warps (tid >= 256)
    float cr0[16], cr1[16], cr2[16], cr3[16];
    if (tid >= 256) {
        const int etid = tid - 256;
        const int b = etid & 63, jg = etid >> 6;
        #pragma unroll
        for (int jj = 0; jj < 16; jj++) {
            int j = jg * 16 + jj;
            float hv = g_init[(size_t)(bb0 + b) * 128 + j];
            float cv = g_init[(size_t)(bb0 + b) * 128 + 64 + j];
            cr0[jj] = cv; cr1[jj] = cv; cr2[jj] = cv; cr3[jj] = cv;
            __half bh = __float2half(hv);
            #pragma unroll
            for (int l = 0; l < 4; l++) hE[(l * 64 + b) * 72 + j] = bh;
        }
    }
    if (tid < 256) stageW(wS, 0, tid);   // prefetch W(layer 0)
    __syncthreads();

    if (tid < 256) {
        // ================= MMA group (warps 0-7) =================
        const int lane = tid & 31, wid = tid >> 5;
        const int m0w = (wid & 1) * 32;
        const int n0w = (wid >> 1) * 64;
        const int sel = lane >> 3, lrow = lane & 7;
        const uint32_t a_laneoff = (uint32_t)(((sel & 1) * 8 + lrow) * 144 + (sel >> 1) * 16);
        const uint32_t b_laneoff = (uint32_t)(((sel & 1) * 8 + lrow) * 272 + (sel >> 1) * 16);
        const int gid = lane >> 2, tig = lane & 3;

        for (int t = 0; t < T; t++) {
            for (int l = 0; l < 4; l++) {
                cp_wait0();
                BAR_SYNC(3, 256);           // W(l) fully staged (all MMA warps)

                // acc init = bias (per-column, fp32)
                float acc[2][8][4];
                #pragma unroll
                for (int nt = 0; nt < 8; nt++) {
                    int col = n0w + nt * 8 + 2 * tig;
                    float b0 = biasS[l * 256 + col];
                    float b1 = biasS[l * 256 + col + 1];
                    #pragma unroll
                    for (int mt = 0; mt < 2; mt++) {
                        acc[mt][nt][0] = b0; acc[mt][nt][1] = b1;
                        acc[mt][nt][2] = b0; acc[mt][nt][3] = b1;
                    }
                }

                // recurrent half: A = h[l] (t-1) — independent of EPI(l-1)
                CHUNK1(hS + (uint32_t)(l * 9216), 0);

                BAR_SYNC(2, 512);           // EPI(l-1) done: h[l-1] fresh, Gt free

                // input half: A = h[l-1] (fresh)
                if (l > 0)
                    CHUNK1(hS + (uint32_t)((l - 1) * 9216), 4);

                // write gate pre-activations: Gt2[j][b][gate] via STS.64
                #pragma unroll
                for (int mt = 0; mt < 2; mt++)
                    #pragma unroll
                    for (int nt = 0; nt < 8; nt++) {
                        int col = n0w + nt * 8 + 2 * tig;
                        int j = col >> 2, g = col & 3;
                        int row = m0w + mt * 16 + gid;
                        uint32_t a0 = gtS + (uint32_t)((j * GT_JS + row * 4 + g) * 4);
                        sts64(a0,       acc[mt][nt][0], acc[mt][nt][1]);
                        sts64(a0 + 128, acc[mt][nt][2], acc[mt][nt][3]);   // row+8
                    }
                BAR_ARRIVE(1, 512);         // Gt(l) ready -> EPI

                BAR_SYNC(3, 256);           // all MMA warps done reading W(l)
                if (!(t == T - 1 && l == 3)) stageW(wS, (l + 1) & 3, tid);
            }
        }
    } else {
        // ================= EPI group (warps 8-15) =================
        const int etid = tid - 256;
        const int b = etid & 63, jg = etid >> 6;

        BAR_ARRIVE(2, 512);                 // prime: "EPI(-1) done"
        for (int t = 0; t < T; t++) {
            for (int l = 0; l < 4; l++) {
                BAR_SYNC(1, 512);           // Gt(l) ready
                switch (l) {
                    case 0: EPI(0, cr0); break;
                    case 1: EPI(1, cr1); break;
                    case 2: EPI(2, cr2); break;
                    default: EPI(3, cr3); break;
                }
                if (l == 3) {
                    BAR_SYNC(4, 256);       // h3 visible across EPI warps
                    if (etid < 192) {
                        int jo = etid >> 6;
                        float a = boS[jo];
                        #pragma unroll 8
                        for (int j = 0; j < 64; j++)
                            a += woS[jo * 64 + j] * __half2float(hE[(192 + b) * 72 + j]);
                        out[(size_t)(bb0 + b) * (3 * T) + (size_t)t * 3 + jo] = a;
                        xS[jo * 64 + b] = a;
                    }
                }
                BAR_ARRIVE(2, 512);         // EPI(l) done
            }
        }
    }
}

// ---------------- entry ----------------
extern "C" void kernel_launch(void* const* d_in, const int* in_sizes, int n_in,
                              void* d_out, int out_size) {
    const float* conds     = (const float*)d_in[0];
    const float* W1        = (const float*)d_in[1];
    const float* b1        = (const float*)d_in[2];
    const float* W2        = (const float*)d_in[3];
    const float* b2        = (const float*)d_in[4];
    const float* W_ih0     = (const float*)d_in[5];
    const float* W_ih_rest = (const float*)d_in[6];
    const float* W_hh      = (const float*)d_in[7];
    const float* b_ih      = (const float*)d_in[8];
    const float* b_hh      = (const float*)d_in[9];
    const float* Wo        = (const float*)d_in[10];
    const float* bo        = (const float*)d_in[11];

    int B = in_sizes[0] / 8;
    if (B > B_MAX) B = B_MAX;
    int T = out_size / (B * 3);

    cudaFuncSetAttribute(lstm_main, cudaFuncAttributeMaxDynamicSharedMemorySize, SMEM_REQ);

    prologue_k<<<B, 128>>>(conds, W1, b1, W2, b2, W_hh, W_ih_rest);
    lstm_main<<<B / 64, 512, SMEM_REQ>>>(b_ih, b_hh, W_ih0, Wo, bo, (float*)d_out, T);
}

// round 14
// speedup vs baseline: 1.7962x; 1.0281x over previous
#include <cuda_runtime.h>
#include <cuda_fp16.h>
#include <cstdint>

#define B_MAX 65536

// ---------------- device scratch (no allocs allowed) ----------------
// repacked weights fp16: [l][khalf][n'=4j+gate : 256][kc : 72 (64+pad)]
// khalf 0 = recurrent (k 0..63), khalf 1 = input (k 64..127; zero for l==0)
__device__ __align__(16) __half g_wm[4][2][256][72];
__device__ float g_init[(size_t)B_MAX * 128];   // [b][128] = (h0 | c0)

// ---------------- math (HW tanh; sigmoid via tanh identity) ----------------
__device__ __forceinline__ float tanh_(float x) {
    float y; asm("tanh.approx.f32 %0, %1;" : "=f"(y) : "f"(x)); return y;
}
__device__ __forceinline__ float sigm(float x) {
    return fmaf(tanh_(0.5f * x), 0.5f, 0.5f);
}

// ---------------- PTX helpers (portable sm_80+) ----------------
__device__ __forceinline__ uint32_t s32(const void* p) { return (uint32_t)__cvta_generic_to_shared(p); }
__device__ __forceinline__ void cp16(uint32_t dst, const void* src) {
    asm volatile("cp.async.cg.shared.global [%0], [%1], 16;" :: "r"(dst), "l"(src));
}
__device__ __forceinline__ void cp_commit() { asm volatile("cp.async.commit_group;" ::: "memory"); }
__device__ __forceinline__ void cp_wait0()  { asm volatile("cp.async.wait_group 0;" ::: "memory"); }
__device__ __forceinline__ void cp_wait1()  { asm volatile("cp.async.wait_group 1;" ::: "memory"); }

__device__ __forceinline__ void ldsm4(uint32_t r[4], uint32_t addr) {
    asm volatile("ldmatrix.sync.aligned.m8n8.x4.shared.b16 {%0,%1,%2,%3}, [%4];"
        : "=r"(r[0]), "=r"(r[1]), "=r"(r[2]), "=r"(r[3]) : "r"(addr));
}
__device__ __forceinline__ void mma16816(float d[4], const uint32_t a[4], uint32_t b0, uint32_t b1) {
    asm volatile("mma.sync.aligned.m16n8k16.row.col.f32.f16.f16.f32 "
        "{%0,%1,%2,%3}, {%4,%5,%6,%7}, {%8,%9}, {%0,%1,%2,%3};"
        : "+f"(d[0]), "+f"(d[1]), "+f"(d[2]), "+f"(d[3])
        : "r"(a[0]), "r"(a[1]), "r"(a[2]), "r"(a[3]), "r"(b0), "r"(b1));
}
__device__ __forceinline__ void sts64(uint32_t addr, float a, float b) {
    asm volatile("st.shared.v2.f32 [%0], {%1,%2};" :: "r"(addr), "f"(a), "f"(b) : "memory");
}
__device__ __forceinline__ void lds128(float4& v, uint32_t addr) {
    asm volatile("ld.shared.v4.f32 {%0,%1,%2,%3}, [%4];"
        : "=f"(v.x), "=f"(v.y), "=f"(v.z), "=f"(v.w) : "r"(addr));
}
__device__ __forceinline__ void sts128(uint32_t addr, const uint32_t r[4]) {
    asm volatile("st.shared.v4.b32 [%0], {%1,%2,%3,%4};"
        :: "r"(addr), "r"(r[0]), "r"(r[1]), "r"(r[2]), "r"(r[3]) : "memory");
}

#define BAR_ARRIVE(id, cnt) asm volatile("bar.arrive %0, %1;" :: "r"(id), "r"(cnt) : "memory")
#define BAR_SYNC(id, cnt)   asm volatile("bar.sync %0, %1;"   :: "r"(id), "r"(cnt) : "memory")

// ---------------- SMEM layout (bytes from 1024-aligned base) ----------------
#define GT_JS 272         // Gt j-stride in words
#define W_HALF 36864      // 256 rows x 144B
#define OFF_H    0        // h: [l:4][m:64][k:72] fp16 = 36864 (144B rows)
#define OFF_W    36864    // bufA + bufB = 73728
#define OFF_GT   110592   // 64*272*4 = 69632
#define OFF_BIAS 180224   // [4][256] f32 (n'=4j+g order) = 4096
#define OFF_WI0  184320   // [256][3] f32 = 3072
#define OFF_WO   187392   // [3][64] f32 = 768
#define OFF_BO   188160   // 16
#define OFF_X    188176   // [3][64] f32 = 768
#define SMEM_USE 188944
#define SMEM_REQ (SMEM_USE + 1024)

// ---------------- single prologue: weight repack + decoder_fc ----------------
__global__ void prologue_k(const float* __restrict__ conds,
                           const float* __restrict__ W1, const float* __restrict__ b1,
                           const float* __restrict__ W2, const float* __restrict__ b2,
                           const float* __restrict__ W_hh, const float* __restrict__ W_ih_rest) {
    const int b = blockIdx.x;
    const int t = threadIdx.x;  // 128

    // ---- repack slice (blocks 0..1151) ----
    int idx = b * 128 + t;
    if (idx < 4 * 2 * 256 * 72) {
        int kc = idx % 72, r = (idx / 72) & 255;
        int half = (idx / (72 * 256)) & 1, l = idx / (72 * 512);
        float v = 0.f;
        if (kc < 64) {
            int j = r >> 2, g = r & 3, n = g * 64 + j;
            if (half == 0)    v = W_hh[(l * 256 + n) * 64 + kc];
            else if (l > 0)   v = W_ih_rest[((l - 1) * 256 + n) * 64 + kc];
        }
        g_wm[l][half][r][kc] = __float2half(v);
    }

    // ---- embed for batch row b ----
    __shared__ float hid[64];
    __shared__ float cnd[8];
    if (t < 8) cnd[t] = conds[b * 8 + t];
    __syncthreads();
    if (t < 64) {
        float a = b1[t];
        #pragma unroll
        for (int k = 0; k < 8; k++) a += cnd[k] * W1[t * 8 + k];
        hid[t] = fmaxf(a, 0.f);
    }
    __syncthreads();
    float a = b2[t];
    #pragma unroll
    for (int k = 0; k < 64; k++) a += hid[k] * W2[t * 64 + k];
    g_init[(size_t)b * 128 + t] = a;
}

// stage one W half-image (36864 B) — MMA threads (tid<256)
__device__ __forceinline__ void stageWh(uint32_t dst, int l, int half, int tid) {
    const char* src = (const char*)&g_wm[l][half][0][0];
    #pragma unroll
    for (int n = 0; n < 9; n++)
        cp16(dst + (uint32_t)(tid * 16 + n * 4096), src + tid * 16 + n * 4096);
    cp_commit();
}

// One K=64 block: A from h (144B rows), B from a W half-buffer (144B rows).
#define CHUNK1(ABASE, WBASE)                                                           \
{                                                                                      \
    _Pragma("unroll")                                                                  \
    for (int ki = 0; ki < 4; ki++) {                                                   \
        uint32_t ah_[2][4];                                                            \
        _Pragma("unroll")                                                              \
        for (int mt = 0; mt < 2; mt++)                                                 \
            ldsm4(ah_[mt], (ABASE) + (uint32_t)((m0w + mt * 16) * 144 + ki * 32) + laneoff); \
        _Pragma("unroll")                                                              \
        for (int np = 0; np < 4; np++) {                                               \
            uint32_t bf_[4];                                                           \
            ldsm4(bf_, (WBASE) + (uint32_t)((n0w + np * 16) * 144 + ki * 32) + laneoff); \
            _Pragma("unroll")                                                          \
            for (int mt = 0; mt < 2; mt++) {                                           \
                mma16816(acc[mt][2 * np],     ah_[mt], bf_[0], bf_[2]);                \
                mma16816(acc[mt][2 * np + 1], ah_[mt], bf_[1], bf_[3]);                \
            }                                                                          \
        }                                                                              \
    }                                                                                  \
}

// EPI half: HALF=0 -> j = jg*8 + jj (jj 0..7); HALF=1 -> j = 32 + jg*8 + (jj-8)
#define EPI_H(L, CR, HALF)                                                             \
{                                                                                      \
    float x0 = 0.f, x1 = 0.f, x2 = 0.f;                                                \
    if ((L) == 0) { x0 = xS[b]; x1 = xS[64 + b]; x2 = xS[128 + b]; }                   \
    uint32_t hh[4];                                                                    \
    _Pragma("unroll")                                                                  \
    for (int jj = (HALF) * 8; jj < (HALF) * 8 + 8; jj++) {                             \
        int j = (HALF) * 32 + jg * 8 + (jj - (HALF) * 8);                              \
        float4 gv;                                                                     \
        lds128(gv, gtS + (uint32_t)((j * GT_JS + b * 4) * 4));                         \
        float vi = gv.x, vf = gv.y, vg = gv.z, vo = gv.w;                              \
        if ((L) == 0) {                                                                \
            vi += x0 * wi0S[j * 3] + x1 * wi0S[j * 3 + 1] + x2 * wi0S[j * 3 + 2];      \
            vf += x0 * wi0S[(64 + j) * 3] + x1 * wi0S[(64 + j) * 3 + 1] + x2 * wi0S[(64 + j) * 3 + 2];   \
            vg += x0 * wi0S[(128 + j) * 3] + x1 * wi0S[(128 + j) * 3 + 1] + x2 * wi0S[(128 + j) * 3 + 2]; \
            vo += x0 * wi0S[(192 + j) * 3] + x1 * wi0S[(192 + j) * 3 + 1] + x2 * wi0S[(192 + j) * 3 + 2]; \
        }                                                                              \
        float cn = sigm(vf) * CR[jj] + sigm(vi) * tanh_(vg);                           \
        CR[jj] = cn;                                                                   \
        float hn = sigm(vo) * tanh_(cn);                                               \
        uint32_t hu = (uint32_t)__half_as_ushort(__float2half(hn));                    \
        int u = jj - (HALF) * 8;                                                       \
        if (u & 1) hh[u >> 1] |= hu << 16; else hh[u >> 1] = hu;                       \
    }                                                                                  \
    sts128(hS + (uint32_t)(((L) * 64 + b) * 144 + (HALF) * 64 + jg * 16), hh);         \
}

__global__ __launch_bounds__(512, 1)
void lstm_main(const float* __restrict__ b_ih, const float* __restrict__ b_hh,
               const float* __restrict__ W_ih0,
               const float* __restrict__ Wo, const float* __restrict__ bo,
               float* __restrict__ out, int T) {
    extern __shared__ char raw[];
    char* basep = (char*)(((uintptr_t)raw + 1023) & ~(uintptr_t)1023);
    const uint32_t hS  = s32(basep + OFF_H);
    const uint32_t wA  = s32(basep + OFF_W);
    const uint32_t wB  = wA + W_HALF;
    const uint32_t gtS = s32(basep + OFF_GT);
    __half* hE   = (__half*)(basep + OFF_H);
    float* biasS = (float*)(basep + OFF_BIAS);
    float* wi0S  = (float*)(basep + OFF_WI0);
    float* woS   = (float*)(basep + OFF_WO);
    float* boS   = (float*)(basep + OFF_BO);
    float* xS    = (float*)(basep + OFF_X);

    const int tid = threadIdx.x;
    const int bb0 = blockIdx.x * 64;

    // ---- stage small params (all 512 threads) ----
    for (int i = tid; i < 1024; i += 512) {
        int l = i >> 8, n = i & 255, g = n >> 6, j = n & 63;
        biasS[l * 256 + 4 * j + g] = b_ih[i] + b_hh[i];
    }
    for (int i = tid; i < 768;  i += 512) wi0S[i] = W_ih0[i];
    if (tid < 192) woS[tid] = Wo[tid];
    if (tid < 3)   boS[tid] = bo[tid];
    if (tid < 64)  { xS[tid] = 0.5f; xS[64 + tid] = 0.5f; xS[128 + tid] = 0.f; }

    // c-state lives in EPI warps (tid >= 256); mapping matches EPI_H
    float cr0[16], cr1[16], cr2[16], cr3[16];
    if (tid >= 256) {
        const int etid = tid - 256;
        const int b = etid & 63, jg = etid >> 6;
        #pragma unroll
        for (int jj = 0; jj < 16; jj++) {
            int j = (jj < 8) ? (jg * 8 + jj) : (32 + jg * 8 + jj - 8);
            float hv = g_init[(size_t)(bb0 + b) * 128 + j];
            float cv = g_init[(size_t)(bb0 + b) * 128 + 64 + j];
            cr0[jj] = cv; cr1[jj] = cv; cr2[jj] = cv; cr3[jj] = cv;
            __half bh = __float2half(hv);
            #pragma unroll
            for (int l = 0; l < 4; l++) hE[(l * 64 + b) * 72 + j] = bh;
        }
    }
    if (tid < 256) {       // prime: A(0), B(0)  -> 2 groups outstanding
        stageWh(wA, 0, 0, tid);
        stageWh(wB, 0, 1, tid);
    }
    __syncthreads();

    if (tid < 256) {
        // ================= MMA group (warps 0-7) =================
        const int lane = tid & 31, wid = tid >> 5;
        const int m0w = (wid & 1) * 32;
        const int n0w = (wid >> 1) * 64;
        const int sel = lane >> 3, lrow = lane & 7;
        const uint32_t laneoff = (uint32_t)(((sel & 1) * 8 + lrow) * 144 + (sel >> 1) * 16);
        const int gid = lane >> 2, tig = lane & 3;
        const bool loN = (wid < 4);   // owns cols 0..127 (units j<32)

        for (int t = 0; t < T; t++) {
            for (int l = 0; l < 4; l++) {
                const bool last = (t == T - 1 && l == 3);
                const int lnxt = (l + 1) & 3;

                cp_wait1();                 // A(l) resident (outstanding: A(l), B(l))
                BAR_SYNC(3, 256);

                // acc init = bias (per-column, fp32)
                float acc[2][8][4];
                #pragma unroll
                for (int nt = 0; nt < 8; nt++) {
                    int col = n0w + nt * 8 + 2 * tig;
                    float b0 = biasS[l * 256 + col];
                    float b1 = biasS[l * 256 + col + 1];
                    #pragma unroll
                    for (int mt = 0; mt < 2; mt++) {
                        acc[mt][nt][0] = b0; acc[mt][nt][1] = b1;
                        acc[mt][nt][2] = b0; acc[mt][nt][3] = b1;
                    }
                }

                // recurrent half: A = h[l] (t-1)
                CHUNK1(hS + (uint32_t)(l * 9216), wA);

                BAR_SYNC(3, 256);           // all MMA warps done reading bufA
                if (!last) stageWh(wA, lnxt, 0, tid);   // A(l+1): outstanding B(l), A(l+1)

                if (last) cp_wait0(); else cp_wait1();  // B(l) resident
                BAR_SYNC(2, 512);           // EPI(l-1) done (also syncs MMA group)

                // input half: A = h[l-1] (fresh)
                if (l > 0)
                    CHUNK1(hS + (uint32_t)((l - 1) * 9216), wB);

                // write gate pre-activations: Gt2[j][b][gate] via STS.64
                #pragma unroll
                for (int mt = 0; mt < 2; mt++)
                    #pragma unroll
                    for (int nt = 0; nt < 8; nt++) {
                        int col = n0w + nt * 8 + 2 * tig;
                        int j = col >> 2, g = col & 3;
                        int row = m0w + mt * 16 + gid;
                        uint32_t a0 = gtS + (uint32_t)((j * GT_JS + row * 4 + g) * 4);
                        sts64(a0,       acc[mt][nt][0], acc[mt][nt][1]);
                        sts64(a0 + 128, acc[mt][nt][2], acc[mt][nt][3]);   // row+8
                    }
                if (loN) BAR_ARRIVE(5, 384);   // Gt half j<32 ready
                else     BAR_ARRIVE(6, 384);   // Gt half j>=32 ready

                BAR_SYNC(3, 256);           // all MMA warps done reading bufB
                if (!last) stageWh(wB, lnxt, 1, tid);   // B(l+1): outstanding A(l+1), B(l+1)
            }
        }
    } else {
        // ================= EPI group (warps 8-15) =================
        const int etid = tid - 256;
        const int b = etid & 63, jg = etid >> 6;

        BAR_ARRIVE(2, 512);                 // prime: "EPI(-1) done"
        for (int t = 0; t < T; t++) {
            for (int l = 0; l < 4; l++) {
                BAR_SYNC(5, 384);           // Gt half j<32 ready
                switch (l) {
                    case 0: EPI_H(0, cr0, 0); break;
                    case 1: EPI_H(1, cr1, 0); break;
                    case 2: EPI_H(2, cr2, 0); break;
                    default: EPI_H(3, cr3, 0); break;
                }
                BAR_SYNC(6, 384);           // Gt half j>=32 ready
                switch (l) {
                    case 0: EPI_H(0, cr0, 1); break;
                    case 1: EPI_H(1, cr1, 1); break;
                    case 2: EPI_H(2, cr2, 1); break;
                    default: EPI_H(3, cr3, 1); break;
                }
                if (l == 3) {
                    BAR_SYNC(4, 256);       // h3 visible across EPI warps
                    if (etid < 192) {
                        int jo = etid >> 6;
                        float a = boS[jo];
                        #pragma unroll 8
                        for (int j = 0; j < 64; j++)
                            a += woS[jo * 64 + j] * __half2float(hE[(192 + b) * 72 + j]);
                        out[(size_t)(bb0 + b) * (3 * T) + (size_t)t * 3 + jo] = a;
                        xS[jo * 64 + b] = a;
                    }
                }
                BAR_ARRIVE(2, 512);         // EPI(l) done
            }
        }
    }
}

// ---------------- entry ----------------
extern "C" void kernel_launch(void* const* d_in, const int* in_sizes, int n_in,
                              void* d_out, int out_size) {
    const float* conds     = (const float*)d_in[0];
    const float* W1        = (const float*)d_in[1];
    const float* b1        = (const float*)d_in[2];
    const float* W2        = (const float*)d_in[3];
    const float* b2        = (const float*)d_in[4];
    const float* W_ih0     = (const float*)d_in[5];
    const float* W_ih_rest = (const float*)d_in[6];
    const float* W_hh      = (const float*)d_in[7];
    const float* b_ih      = (const float*)d_in[8];
    const float* b_hh      = (const float*)d_in[9];
    const float* Wo        = (const float*)d_in[10];
    const float* bo        = (const float*)d_in[11];

    int B = in_sizes[0] / 8;
    if (B > B_MAX) B = B_MAX;
    int T = out_size / (B * 3);

    cudaFuncSetAttribute(lstm_main, cudaFuncAttributeMaxDynamicSharedMemorySize, SMEM_REQ);

    prologue_k<<<B, 128>>>(conds, W1, b1, W2, b2, W_hh, W_ih_rest);
    lstm_main<<<B / 64, 512, SMEM_REQ>>>(b_ih, b_hh, W_ih0, Wo, bo, (float*)d_out, T);
}